// round 16
// baseline (speedup 1.0000x reference)
#include <cuda_runtime.h>
#include <cuda_fp16.h>
#include <math.h>
#include <stdint.h>

// Problem constants
#define NB 8
#define LL 2048
#define NTOK (NB*LL)        // 16384
#define DD 1024
#define EE 8
#define HH 2048

#define BM 128
#define BN 256
#define BK 64
#define NSTAGE 3
#define ATILE_BYTES 16384       // 128 rows x 128B
#define BTILE_BYTES 32768       // 256 rows x 128B
#define STAGE_BYTES (ATILE_BYTES + BTILE_BYTES)   // 49152
#define OFF_B ATILE_BYTES
#define OFF_TOK 0
#define OFF_TILE 1024
#define SMEM_TOTAL (OFF_TILE + NSTAGE * STAGE_BYTES)   // 148480

// -------------------- device scratch (no allocs allowed) --------------------
__device__ __half g_xh[(size_t)NTOK * DD];
__device__ __half g_w1h[(size_t)EE * HH * DD];   // [E][H][D]  (W1^T)
__device__ __half g_w2h[(size_t)EE * DD * HH];   // [E][D][H]  (W2^T)
__device__ __half g_h[(size_t)NTOK * HH];        // permuted hidden
__device__ int   g_perm[NTOK];
__device__ int   g_topidx[NTOK];
__device__ float g_topw[NTOK];
__device__ int   g_counts[EE];   // zero at module load; scan re-zeros after use
__device__ int   g_offs[EE + 1];
__device__ int   g_cursor[EE];

// -------------------- PTX helpers (all non-'a' features) --------------------
__device__ __forceinline__ uint32_t smem_u32(const void* p) {
    uint32_t a;
    asm("{ .reg .u64 t; cvta.to.shared.u64 t, %1; cvt.u32.u64 %0, t; }" : "=r"(a) : "l"(p));
    return a;
}
__device__ __forceinline__ void cp16(uint32_t dst, const void* src) {
    asm volatile("cp.async.cg.shared.global [%0], [%1], 16;" :: "r"(dst), "l"(src));
}
#define CP_COMMIT() asm volatile("cp.async.commit_group;" ::: "memory")
#define CP_WAIT(n)  asm volatile("cp.async.wait_group %0;" :: "n"(n) : "memory")

__device__ __forceinline__ void ldsm4(uint32_t* r, uint32_t addr) {
    asm volatile("ldmatrix.sync.aligned.m8n8.x4.shared.b16 {%0,%1,%2,%3}, [%4];"
                 : "=r"(r[0]), "=r"(r[1]), "=r"(r[2]), "=r"(r[3]) : "r"(addr));
}
__device__ __forceinline__ void mma16816(float* c, const uint32_t* a, const uint32_t* b) {
    asm volatile("mma.sync.aligned.m16n8k16.row.col.f32.f16.f16.f32 "
        "{%0,%1,%2,%3}, {%4,%5,%6,%7}, {%8,%9}, {%0,%1,%2,%3};"
        : "+f"(c[0]), "+f"(c[1]), "+f"(c[2]), "+f"(c[3])
        : "r"(a[0]), "r"(a[1]), "r"(a[2]), "r"(a[3]), "r"(b[0]), "r"(b[1]));
}

// ------- gating (fused x->fp16 conversion; Wg staged transposed in smem) -----
__global__ void gate_kernel(const float* __restrict__ x,
                            const float* __restrict__ Wg,
                            const float* __restrict__ bg,
                            float* __restrict__ gw_out) {
    __shared__ float wgs[EE][DD];        // 32KB, WgT: [expert][k]
    const int tid = threadIdx.x;
    for (int i = tid; i < DD * EE / 4; i += 256) {
        float4 v = ((const float4*)Wg)[i];
        int k = i >> 1, e0 = (i & 1) * 4;
        wgs[e0 + 0][k] = v.x;
        wgs[e0 + 1][k] = v.y;
        wgs[e0 + 2][k] = v.z;
        wgs[e0 + 3][k] = v.w;
    }
    __syncthreads();

    int warp = tid >> 5;
    int lane = tid & 31;
    int t = blockIdx.x * 8 + warp;
    if (t >= NTOK) return;

    const float* xr = x + (size_t)t * DD;
    float xv[32];
#pragma unroll
    for (int i = 0; i < 32; i++) xv[i] = xr[lane + 32 * i];

    __half* xh = g_xh + (size_t)t * DD;
#pragma unroll
    for (int i = 0; i < 32; i++) xh[lane + 32 * i] = __float2half_rn(xv[i]);

    float logit[EE];
#pragma unroll
    for (int e = 0; e < EE; e++) {
        float s = 0.f;
#pragma unroll
        for (int i = 0; i < 32; i++) s += xv[i] * wgs[e][lane + 32 * i];
#pragma unroll
        for (int o = 16; o > 0; o >>= 1) s += __shfl_xor_sync(0xffffffffu, s, o);
        logit[e] = s + bg[e];
    }

    if (lane == 0) {
        float mx = logit[0]; int bi = 0;
#pragma unroll
        for (int e = 1; e < EE; e++) if (logit[e] > mx) { mx = logit[e]; bi = e; }
        float p[EE]; float se = 0.f;
#pragma unroll
        for (int e = 0; e < EE; e++) { p[e] = expf(logit[e] - mx); se += p[e]; }
        float inv = 1.f / se;
#pragma unroll
        for (int e = 0; e < EE; e++) gw_out[(size_t)t * EE + e] = p[e] * inv;
        g_topidx[t] = bi;
        g_topw[t]  = p[bi] * inv;
        atomicAdd(&g_counts[bi], 1);
    }
}

// -------------------- scan: offsets + cursor, then re-zero counts ------------
__global__ void scan_kernel() {
    int s = 0;
    g_offs[0] = 0;
    for (int e = 0; e < EE; e++) {
        g_cursor[e] = s;
        s += g_counts[e];
        g_offs[e + 1] = s;
        g_counts[e] = 0;          // ready for next kernel_launch invocation
    }
}

// ------------ prep: W1 convert/transpose + scatter (W2 moved to ffn1) --------
// blocks [0, 32768): W1 tiles (64 n-tiles x 32 k-tiles x 8 experts, half idle)
// blocks [32768, 32832): scatter
__global__ void prep_kernel(const float* __restrict__ W1) {
    const int bid = blockIdx.x;
    const int tid = threadIdx.x;
    if (bid >= 32768) {
        int t = (bid - 32768) * 256 + tid;
        if (t < NTOK) {
            int e = g_topidx[t];
            int pos = atomicAdd(&g_cursor[e], 1);
            g_perm[pos] = t;
        }
        return;
    }
    const int bx = bid & 63, by = (bid >> 6) & 63, bz = bid >> 12;   // bz 0..7
    if (by >= DD / 32) return;
    const float* src = W1 + (size_t)bz * DD * HH;        // K=DD, N=HH
    __half* dh = g_w1h + (size_t)bz * HH * DD;
    __shared__ float t[32][33];
    const int tx = tid & 31, ty = tid >> 5;
    const int n0 = bx * 32, k0 = by * 32;
#pragma unroll
    for (int i = 0; i < 4; i++)
        t[ty + i * 8][tx] = src[(size_t)(k0 + ty + i * 8) * HH + n0 + tx];
    __syncthreads();
#pragma unroll
    for (int i = 0; i < 4; i++) {
        float v = t[tx][ty + i * 8];
        size_t o = (size_t)(n0 + ty + i * 8) * DD + (k0 + tx);
        dh[o] = __float2half_rn(v);
    }
}

// -------------------- mma.sync MoE GEMM (fp16), 128x256 tile, warp 64x64 -----
// SMEM rows 128B = 64 fp16 (k-dim), 16B chunks swizzled by (row&7).
// MODE 0 grid has an extra z-slice (z==EE): 1024 blocks converting W2 -> g_w2h,
// scheduled after the GEMM blocks and absorbed into ffn1's idle DRAM/issue slots.
#define LOAD_ROW(ptr, db) do { \
    cp16((db) + ((0u ^ swr) << 4), (ptr) + 0);  cp16((db) + ((1u ^ swr) << 4), (ptr) + 8); \
    cp16((db) + ((2u ^ swr) << 4), (ptr) + 16); cp16((db) + ((3u ^ swr) << 4), (ptr) + 24); \
    cp16((db) + ((4u ^ swr) << 4), (ptr) + 32); cp16((db) + ((5u ^ swr) << 4), (ptr) + 40); \
    cp16((db) + ((6u ^ swr) << 4), (ptr) + 48); cp16((db) + ((7u ^ swr) << 4), (ptr) + 56); \
} while (0)

#define LOAD_STAGE(c) do { \
    uint32_t so = OFF_TILE + ((c) % NSTAGE) * STAGE_BYTES; \
    LOAD_ROW(srcp0 + (size_t)(c) * BK, S + so + dst0); \
    if (tid < 128) LOAD_ROW(srcp1 + (size_t)(c) * BK, S + so + dst1); \
} while (0)

template<int MODE>
__global__ __launch_bounds__(256, 1)
void moe_gemm(const float* __restrict__ bias, float* __restrict__ out,
              const float* __restrict__ w2src) {
    constexpr int KTOT = (MODE == 0) ? DD : HH;
    constexpr int NROW = (MODE == 0) ? HH : DD;
    constexpr int NCH  = KTOT / BK;       // 16 or 32

    extern __shared__ char smem[];
    const int tid = threadIdx.x;

    if (MODE == 0 && blockIdx.z == EE) {
        // ---- W2 convert/transpose tail blocks (reuse dynamic smem) ----
        float (*t)[33] = (float(*)[33])smem;
        const int cid = blockIdx.x + blockIdx.y * (HH / BN);   // 0..1023
        const int tx = tid & 31, ty = tid >> 5;
#pragma unroll 1
        for (int i = 0; i < 16; i++) {
            int tt = cid * 16 + i;               // 16384 tiles total
            int e2 = tt >> 11;                   // 2048 tiles/expert
            int kt = (tt >> 5) & 63;             // H k-tile 0..63
            int nt = tt & 31;                    // D n-tile 0..31
            const float* src = w2src + (size_t)e2 * HH * DD;   // [H][D]
            __half* dh = g_w2h + (size_t)e2 * DD * HH;         // [D][H]
            int k0 = kt * 32, n0 = nt * 32;
#pragma unroll
            for (int r = 0; r < 4; r++)
                t[ty + r * 8][tx] = src[(size_t)(k0 + ty + r * 8) * DD + n0 + tx];
            __syncthreads();
#pragma unroll
            for (int r = 0; r < 4; r++) {
                float v = t[tx][ty + r * 8];
                dh[(size_t)(n0 + ty + r * 8) * HH + (k0 + tx)] = __float2half_rn(v);
            }
            __syncthreads();
        }
        return;
    }

    const int e    = blockIdx.z;
    const int base = g_offs[e];
    const int cnt  = g_offs[e + 1] - base;
    const int m0   = blockIdx.y * BM;
    if (m0 >= cnt) return;
    const int n0   = blockIdx.x * BN;

    const uint32_t S = smem_u32(smem);
    int* tok = (int*)(smem + OFF_TOK);

    if (tid < 128) {
        int m = m0 + tid; if (m >= cnt) m = cnt - 1;
        tok[tid] = g_perm[base + m];
    }
    __syncthreads();

    // ---- loader setup ----
    const __half* Abase = (MODE == 0) ? g_xh : g_h;
    const __half* Wbase = (MODE == 0) ? g_w1h : g_w2h;
    const __half* srcp0;
    const __half* srcp1 = nullptr;
    uint32_t dst0, dst1 = 0;
    const uint32_t swr = (uint32_t)(tid & 7);
    if (tid < 128) {
        size_t rowA;
        if (MODE == 0) rowA = (size_t)tok[tid];
        else { int m = m0 + tid; if (m >= cnt) m = cnt - 1; rowA = (size_t)(base + m); }
        srcp0 = Abase + rowA * KTOT;
        dst0  = (uint32_t)tid * 128;                       // A region
        srcp1 = Wbase + ((size_t)e * NROW + n0 + 128 + tid) * KTOT;
        dst1  = OFF_B + (uint32_t)(128 + tid) * 128;       // B rows 128-255
    } else {
        srcp0 = Wbase + ((size_t)e * NROW + n0 + (tid - 128)) * KTOT;
        dst0  = OFF_B + (uint32_t)(tid - 128) * 128;       // B rows 0-127
    }

    // ---- fragment addressing: 8 warps = 2 (M) x 4 (N), warp tile 64x64 ----
    const int lane = tid & 31, wid = tid >> 5;
    const int wm = wid >> 2, wn = wid & 3;
    const uint32_t rA  = lane & 15;
    const uint32_t cA  = lane >> 4;
    const uint32_t swA = rA & 7;
    uint32_t rowA_s[4];
#pragma unroll
    for (int i = 0; i < 4; i++) rowA_s[i] = (uint32_t)(wm * 64 + i * 16 + rA) * 128;
    const uint32_t rB  = (lane & 7) | ((lane >> 1) & 8);
    const uint32_t cB  = (lane >> 3) & 1;
    const uint32_t swB = rB & 7;
    uint32_t rowB_s[4];
#pragma unroll
    for (int jj = 0; jj < 4; jj++) rowB_s[jj] = OFF_B + (uint32_t)(wn * 64 + jj * 16 + rB) * 128;

    float C[4][8][4];
#pragma unroll
    for (int i = 0; i < 4; i++)
#pragma unroll
        for (int j = 0; j < 8; j++)
#pragma unroll
            for (int q = 0; q < 4; q++) C[i][j][q] = 0.f;

    LOAD_STAGE(0); CP_COMMIT();
    LOAD_STAGE(1); CP_COMMIT();

    for (int c = 0; c < NCH; c++) {
        CP_WAIT(1);
        __syncthreads();
        if (c + 2 < NCH) LOAD_STAGE(c + 2);
        CP_COMMIT();

        const uint32_t buf = S + OFF_TILE + (uint32_t)(c % NSTAGE) * STAGE_BYTES;
#pragma unroll
        for (int s = 0; s < 4; s++) {          // 4 x k16 per 64-chunk
            const uint32_t kc = 2 * s;
            uint32_t A[4][4], B[4][4];
#pragma unroll
            for (int i = 0; i < 4; i++)
                ldsm4(A[i], buf + rowA_s[i] + (((kc + cA) ^ swA) << 4));
#pragma unroll
            for (int jj = 0; jj < 4; jj++)
                ldsm4(B[jj], buf + rowB_s[jj] + (((kc + cB) ^ swB) << 4));
#pragma unroll
            for (int i = 0; i < 4; i++)
#pragma unroll
                for (int j = 0; j < 8; j++)
                    mma16816(C[i][j], A[i], &B[j >> 1][(j & 1) * 2]);
        }
    }

    // -------- epilogue --------
    const int gcol0 = n0 + wn * 64;
#pragma unroll
    for (int i = 0; i < 4; i++) {
        const int rbase = wm * 64 + i * 16 + (lane >> 2);
#pragma unroll
        for (int half = 0; half < 2; half++) {
            const int rr = rbase + 8 * half;
            const int m  = m0 + rr;
            if (m >= cnt) continue;
            if (MODE == 0) {
                const size_t pb = (size_t)(base + m) * HH;
#pragma unroll
                for (int j = 0; j < 8; j++) {
                    const int cc = gcol0 + j * 8 + (lane & 3) * 2;
                    float v0 = fmaxf(C[i][j][2 * half]     + bias[e * HH + cc],     0.f);
                    float v1 = fmaxf(C[i][j][2 * half + 1] + bias[e * HH + cc + 1], 0.f);
                    *(__half2*)(&g_h[pb + cc]) = __floats2half2_rn(v0, v1);
                }
            } else {
                const int t = tok[rr];
                const float w = g_topw[t];
                float* op = out + (size_t)t * DD;
#pragma unroll
                for (int j = 0; j < 8; j++) {
                    const int cc = gcol0 + j * 8 + (lane & 3) * 2;
                    float2 v;
                    v.x = w * (C[i][j][2 * half]     + bias[e * DD + cc]);
                    v.y = w * (C[i][j][2 * half + 1] + bias[e * DD + cc + 1]);
                    *(float2*)(op + cc) = v;
                }
            }
        }
    }
}

// -------------------- launch --------------------
extern "C" void kernel_launch(void* const* d_in, const int* in_sizes, int n_in,
                              void* d_out, int out_size) {
    const float* x  = (const float*)d_in[0];
    const float* Wg = (const float*)d_in[1];
    const float* bg = (const float*)d_in[2];
    const float* W1 = (const float*)d_in[3];
    const float* b1 = (const float*)d_in[4];
    const float* W2 = (const float*)d_in[5];
    const float* b2 = (const float*)d_in[6];
    float* out = (float*)d_out;
    float* gw  = out + (size_t)NTOK * DD;   // gate_weights appended after `out`

    cudaFuncSetAttribute(moe_gemm<0>, cudaFuncAttributeMaxDynamicSharedMemorySize, SMEM_TOTAL);
    cudaFuncSetAttribute(moe_gemm<1>, cudaFuncAttributeMaxDynamicSharedMemorySize, SMEM_TOTAL);

    gate_kernel<<<NTOK / 8, 256>>>(x, Wg, bg, gw);            // 1 (smem WgT + x->fp16)
    scan_kernel<<<1, 1>>>();                                  // 2 (offs/cursor + re-zero counts)
    prep_kernel<<<32832, 256>>>(W1);                          // 3 (W1 conv + scatter)
    moe_gemm<0><<<dim3(HH / BN, NTOK / BM, EE + 1), 256, SMEM_TOTAL>>>(b1, nullptr, W2); // 4 (ffn1 + W2 conv tail)
    moe_gemm<1><<<dim3(DD / BN, NTOK / BM, EE), 256, SMEM_TOTAL>>>(b2, out, nullptr);    // 5
}

// round 17
// speedup vs baseline: 1.0913x; 1.0913x over previous
#include <cuda_runtime.h>
#include <cuda_fp16.h>
#include <math.h>
#include <stdint.h>

// Problem constants
#define NB 8
#define LL 2048
#define NTOK (NB*LL)        // 16384
#define DD 1024
#define EE 8
#define HH 2048

#define BM 128
#define BN 256
#define BK 64
#define NSTAGE 3
#define ATILE_BYTES 16384       // 128 rows x 128B
#define BTILE_BYTES 32768       // 256 rows x 128B
#define STAGE_BYTES (ATILE_BYTES + BTILE_BYTES)   // 49152
#define OFF_B ATILE_BYTES
#define OFF_TOK 0
#define OFF_TILE 1024
#define SMEM_TOTAL (OFF_TILE + NSTAGE * STAGE_BYTES)   // 148480

// -------------------- device scratch (no allocs allowed) --------------------
__device__ __half g_xh[(size_t)NTOK * DD];
__device__ __half g_w1h[(size_t)EE * HH * DD];   // [E][H][D]  (W1^T)
__device__ __half g_w2h[(size_t)EE * DD * HH];   // [E][D][H]  (W2^T)
__device__ __half g_h[(size_t)NTOK * HH];        // permuted hidden
__device__ int   g_perm[NTOK];
__device__ int   g_topidx[NTOK];
__device__ float g_topw[NTOK];
__device__ int   g_counts[EE];   // zero at module load; re-zeroed by gate's last block
__device__ int   g_offs[EE + 1];
__device__ int   g_cursor[EE];
__device__ int   g_done;         // zero at load; re-zeroed by the last block each run

// -------------------- PTX helpers (all non-'a' features) --------------------
__device__ __forceinline__ uint32_t smem_u32(const void* p) {
    uint32_t a;
    asm("{ .reg .u64 t; cvta.to.shared.u64 t, %1; cvt.u32.u64 %0, t; }" : "=r"(a) : "l"(p));
    return a;
}
__device__ __forceinline__ void cp16(uint32_t dst, const void* src) {
    asm volatile("cp.async.cg.shared.global [%0], [%1], 16;" :: "r"(dst), "l"(src));
}
#define CP_COMMIT() asm volatile("cp.async.commit_group;" ::: "memory")
#define CP_WAIT(n)  asm volatile("cp.async.wait_group %0;" :: "n"(n) : "memory")

__device__ __forceinline__ void ldsm4(uint32_t* r, uint32_t addr) {
    asm volatile("ldmatrix.sync.aligned.m8n8.x4.shared.b16 {%0,%1,%2,%3}, [%4];"
                 : "=r"(r[0]), "=r"(r[1]), "=r"(r[2]), "=r"(r[3]) : "r"(addr));
}
__device__ __forceinline__ void mma16816(float* c, const uint32_t* a, const uint32_t* b) {
    asm volatile("mma.sync.aligned.m16n8k16.row.col.f32.f16.f16.f32 "
        "{%0,%1,%2,%3}, {%4,%5,%6,%7}, {%8,%9}, {%0,%1,%2,%3};"
        : "+f"(c[0]), "+f"(c[1]), "+f"(c[2]), "+f"(c[3])
        : "r"(a[0]), "r"(a[1]), "r"(a[2]), "r"(a[3]), "r"(b[0]), "r"(b[1]));
}

// ---- gating: smem WgT staging amortized over 8 tokens/warp; inline scan -----
#define GATE_BLKS 256
__global__ void gate_kernel(const float* __restrict__ x,
                            const float* __restrict__ Wg,
                            const float* __restrict__ bg,
                            float* __restrict__ gw_out) {
    __shared__ float wgs[EE][DD];        // 32KB, WgT: [expert][k]
    const int tid = threadIdx.x;
    for (int i = tid; i < DD * EE / 4; i += 256) {
        float4 v = ((const float4*)Wg)[i];
        int k = i >> 1, e0 = (i & 1) * 4;
        wgs[e0 + 0][k] = v.x;
        wgs[e0 + 1][k] = v.y;
        wgs[e0 + 2][k] = v.z;
        wgs[e0 + 3][k] = v.w;
    }
    __syncthreads();

    const int warp = tid >> 5;
    const int lane = tid & 31;
    const int wg   = blockIdx.x * 8 + warp;    // 0..2047

    for (int g = 0; g < 8; g++) {
        const int t = wg + 2048 * g;
        const float* xr = x + (size_t)t * DD;
        float xv[32];
#pragma unroll
        for (int i = 0; i < 32; i++) xv[i] = xr[lane + 32 * i];

        __half* xh = g_xh + (size_t)t * DD;
#pragma unroll
        for (int i = 0; i < 32; i++) xh[lane + 32 * i] = __float2half_rn(xv[i]);

        float logit[EE];
#pragma unroll
        for (int e = 0; e < EE; e++) {
            float s = 0.f;
#pragma unroll
            for (int i = 0; i < 32; i++) s += xv[i] * wgs[e][lane + 32 * i];
#pragma unroll
            for (int o = 16; o > 0; o >>= 1) s += __shfl_xor_sync(0xffffffffu, s, o);
            logit[e] = s + bg[e];
        }

        if (lane == 0) {
            float mx = logit[0]; int bi = 0;
#pragma unroll
            for (int e = 1; e < EE; e++) if (logit[e] > mx) { mx = logit[e]; bi = e; }
            float p[EE]; float se = 0.f;
#pragma unroll
            for (int e = 0; e < EE; e++) { p[e] = expf(logit[e] - mx); se += p[e]; }
            float inv = 1.f / se;
#pragma unroll
            for (int e = 0; e < EE; e++) gw_out[(size_t)t * EE + e] = p[e] * inv;
            g_topidx[t] = bi;
            g_topw[t]  = p[bi] * inv;
            atomicAdd(&g_counts[bi], 1);
        }
    }

    // ---- last-block-done inline scan (replaces scan_kernel launch) ----
    __syncthreads();
    if (tid == 0) {
        __threadfence();
        int prev = atomicAdd(&g_done, 1);
        if (prev == GATE_BLKS - 1) {
            g_done = 0;
            int s = 0;
            g_offs[0] = 0;
            for (int e = 0; e < EE; e++) {
                g_cursor[e] = s;
                s += g_counts[e];
                g_offs[e + 1] = s;
                g_counts[e] = 0;
            }
            __threadfence();
        }
    }
}

// -------------------- prep: fused weight-convert/transpose + scatter ---------
__global__ void prep_kernel(const float* __restrict__ W1, const float* __restrict__ W2) {
    const int bid = blockIdx.x;
    const int tid = threadIdx.x;
    if (bid >= 65536) {
        int t = (bid - 65536) * 256 + tid;
        if (t < NTOK) {
            int e = g_topidx[t];
            int pos = atomicAdd(&g_cursor[e], 1);
            g_perm[pos] = t;
        }
        return;
    }
    const int bx = bid & 63, by = (bid >> 6) & 63, bz = bid >> 12;
    const float* src;
    __half* dh;
    int K, N;
    if (bz < EE) {
        src = W1 + (size_t)bz * DD * HH; dh = g_w1h + (size_t)bz * HH * DD;
        K = DD; N = HH;
        if (by >= K / 32) return;
    } else {
        int e = bz - EE;
        src = W2 + (size_t)e * HH * DD; dh = g_w2h + (size_t)e * DD * HH;
        K = HH; N = DD;
        if (bx >= N / 32) return;
    }
    __shared__ float t[32][33];
    const int tx = tid & 31, ty = tid >> 5;
    const int n0 = bx * 32, k0 = by * 32;
#pragma unroll
    for (int i = 0; i < 4; i++)
        t[ty + i * 8][tx] = src[(size_t)(k0 + ty + i * 8) * N + n0 + tx];
    __syncthreads();
#pragma unroll
    for (int i = 0; i < 4; i++) {
        float v = t[tx][ty + i * 8];
        size_t o = (size_t)(n0 + ty + i * 8) * K + (k0 + tx);
        dh[o] = __float2half_rn(v);
    }
}

// -------------------- mma.sync MoE GEMM (fp16), 128x256 tile, warp 64x64 -----
// SMEM rows 128B = 64 fp16 (k-dim), 16B chunks swizzled by (row&7).
#define LOAD_ROW(ptr, db) do { \
    cp16((db) + ((0u ^ swr) << 4), (ptr) + 0);  cp16((db) + ((1u ^ swr) << 4), (ptr) + 8); \
    cp16((db) + ((2u ^ swr) << 4), (ptr) + 16); cp16((db) + ((3u ^ swr) << 4), (ptr) + 24); \
    cp16((db) + ((4u ^ swr) << 4), (ptr) + 32); cp16((db) + ((5u ^ swr) << 4), (ptr) + 40); \
    cp16((db) + ((6u ^ swr) << 4), (ptr) + 48); cp16((db) + ((7u ^ swr) << 4), (ptr) + 56); \
} while (0)

#define LOAD_STAGE(c) do { \
    uint32_t so = OFF_TILE + ((c) % NSTAGE) * STAGE_BYTES; \
    LOAD_ROW(srcp0 + (size_t)(c) * BK, S + so + dst0); \
    if (tid < 128) LOAD_ROW(srcp1 + (size_t)(c) * BK, S + so + dst1); \
} while (0)

template<int MODE>
__global__ __launch_bounds__(256, 1)
void moe_gemm(const float* __restrict__ bias, float* __restrict__ out) {
    constexpr int KTOT = (MODE == 0) ? DD : HH;
    constexpr int NROW = (MODE == 0) ? HH : DD;
    constexpr int NCH  = KTOT / BK;       // 16 or 32

    const int e    = blockIdx.z;
    const int base = g_offs[e];
    const int cnt  = g_offs[e + 1] - base;
    const int m0   = blockIdx.y * BM;
    if (m0 >= cnt) return;
    const int n0   = blockIdx.x * BN;

    extern __shared__ char smem[];
    const uint32_t S = smem_u32(smem);
    int* tok = (int*)(smem + OFF_TOK);
    const int tid = threadIdx.x;

    if (tid < 128) {
        int m = m0 + tid; if (m >= cnt) m = cnt - 1;
        tok[tid] = g_perm[base + m];
    }
    __syncthreads();

    // ---- loader setup ----
    const __half* Abase = (MODE == 0) ? g_xh : g_h;
    const __half* Wbase = (MODE == 0) ? g_w1h : g_w2h;
    const __half* srcp0;
    const __half* srcp1 = nullptr;
    uint32_t dst0, dst1 = 0;
    const uint32_t swr = (uint32_t)(tid & 7);
    if (tid < 128) {
        size_t rowA;
        if (MODE == 0) rowA = (size_t)tok[tid];
        else { int m = m0 + tid; if (m >= cnt) m = cnt - 1; rowA = (size_t)(base + m); }
        srcp0 = Abase + rowA * KTOT;
        dst0  = (uint32_t)tid * 128;                       // A region
        srcp1 = Wbase + ((size_t)e * NROW + n0 + 128 + tid) * KTOT;
        dst1  = OFF_B + (uint32_t)(128 + tid) * 128;       // B rows 128-255
    } else {
        srcp0 = Wbase + ((size_t)e * NROW + n0 + (tid - 128)) * KTOT;
        dst0  = OFF_B + (uint32_t)(tid - 128) * 128;       // B rows 0-127
    }

    // ---- fragment addressing: 8 warps = 2 (M) x 4 (N), warp tile 64x64 ----
    const int lane = tid & 31, wid = tid >> 5;
    const int wm = wid >> 2, wn = wid & 3;
    const uint32_t rA  = lane & 15;
    const uint32_t cA  = lane >> 4;
    const uint32_t swA = rA & 7;
    uint32_t rowA_s[4];
#pragma unroll
    for (int i = 0; i < 4; i++) rowA_s[i] = (uint32_t)(wm * 64 + i * 16 + rA) * 128;
    const uint32_t rB  = (lane & 7) | ((lane >> 1) & 8);
    const uint32_t cB  = (lane >> 3) & 1;
    const uint32_t swB = rB & 7;
    uint32_t rowB_s[4];
#pragma unroll
    for (int jj = 0; jj < 4; jj++) rowB_s[jj] = OFF_B + (uint32_t)(wn * 64 + jj * 16 + rB) * 128;

    float C[4][8][4];
#pragma unroll
    for (int i = 0; i < 4; i++)
#pragma unroll
        for (int j = 0; j < 8; j++)
#pragma unroll
            for (int q = 0; q < 4; q++) C[i][j][q] = 0.f;

    LOAD_STAGE(0); CP_COMMIT();
    LOAD_STAGE(1); CP_COMMIT();

    for (int c = 0; c < NCH; c++) {
        CP_WAIT(1);
        __syncthreads();
        if (c + 2 < NCH) LOAD_STAGE(c + 2);
        CP_COMMIT();

        const uint32_t buf = S + OFF_TILE + (uint32_t)(c % NSTAGE) * STAGE_BYTES;
#pragma unroll
        for (int s = 0; s < 4; s++) {          // 4 x k16 per 64-chunk
            const uint32_t kc = 2 * s;
            uint32_t A[4][4], B[4][4];
#pragma unroll
            for (int i = 0; i < 4; i++)
                ldsm4(A[i], buf + rowA_s[i] + (((kc + cA) ^ swA) << 4));
#pragma unroll
            for (int jj = 0; jj < 4; jj++)
                ldsm4(B[jj], buf + rowB_s[jj] + (((kc + cB) ^ swB) << 4));
#pragma unroll
            for (int i = 0; i < 4; i++)
#pragma unroll
                for (int j = 0; j < 8; j++)
                    mma16816(C[i][j], A[i], &B[j >> 1][(j & 1) * 2]);
        }
    }

    // -------- epilogue --------
    const int gcol0 = n0 + wn * 64;
#pragma unroll
    for (int i = 0; i < 4; i++) {
        const int rbase = wm * 64 + i * 16 + (lane >> 2);
#pragma unroll
        for (int half = 0; half < 2; half++) {
            const int rr = rbase + 8 * half;
            const int m  = m0 + rr;
            if (m >= cnt) continue;
            if (MODE == 0) {
                const size_t pb = (size_t)(base + m) * HH;
#pragma unroll
                for (int j = 0; j < 8; j++) {
                    const int cc = gcol0 + j * 8 + (lane & 3) * 2;
                    float v0 = fmaxf(C[i][j][2 * half]     + bias[e * HH + cc],     0.f);
                    float v1 = fmaxf(C[i][j][2 * half + 1] + bias[e * HH + cc + 1], 0.f);
                    *(__half2*)(&g_h[pb + cc]) = __floats2half2_rn(v0, v1);
                }
            } else {
                const int t = tok[rr];
                const float w = g_topw[t];
                float* op = out + (size_t)t * DD;
#pragma unroll
                for (int j = 0; j < 8; j++) {
                    const int cc = gcol0 + j * 8 + (lane & 3) * 2;
                    float2 v;
                    v.x = w * (C[i][j][2 * half]     + bias[e * DD + cc]);
                    v.y = w * (C[i][j][2 * half + 1] + bias[e * DD + cc + 1]);
                    *(float2*)(op + cc) = v;
                }
            }
        }
    }
}

// -------------------- launch --------------------
extern "C" void kernel_launch(void* const* d_in, const int* in_sizes, int n_in,
                              void* d_out, int out_size) {
    const float* x  = (const float*)d_in[0];
    const float* Wg = (const float*)d_in[1];
    const float* bg = (const float*)d_in[2];
    const float* W1 = (const float*)d_in[3];
    const float* b1 = (const float*)d_in[4];
    const float* W2 = (const float*)d_in[5];
    const float* b2 = (const float*)d_in[6];
    float* out = (float*)d_out;
    float* gw  = out + (size_t)NTOK * DD;   // gate_weights appended after `out`

    cudaFuncSetAttribute(moe_gemm<0>, cudaFuncAttributeMaxDynamicSharedMemorySize, SMEM_TOTAL);
    cudaFuncSetAttribute(moe_gemm<1>, cudaFuncAttributeMaxDynamicSharedMemorySize, SMEM_TOTAL);

    gate_kernel<<<GATE_BLKS, 256>>>(x, Wg, bg, gw);           // 1 (gate + inline scan)
    prep_kernel<<<65600, 256>>>(W1, W2);                      // 2 (convw + scatter fused)
    moe_gemm<0><<<dim3(HH / BN, NTOK / BM, EE), 256, SMEM_TOTAL>>>(b1, nullptr);  // 3 <- ncu? (index shifts)
    moe_gemm<1><<<dim3(DD / BN, NTOK / BM, EE), 256, SMEM_TOTAL>>>(b2, out);      // 4
}